// round 10
// baseline (speedup 1.0000x reference)
#include <cuda_runtime.h>
#include <cstdint>
#include <cstddef>

// FPS with EXACT spatial pruning, lean dataflow.
// B=8, N=131072, NPOINT=1024. 8 clusters x 8 CTAs x 512 threads.
// One-time Morton(32^3) counting sort -> g_reorder (xyz + orig idx).
// 256 groups/CTA of 64 pts; warp w statically owns groups k%16==w.
// Per step: lanes check skip bound (exact), warp iterates active groups
// (prefetch-pipelined L2 loads), updates SMEM mindist, REDUX -> meta[k];
// warp REDUXes its 16 metas -> warpred; warp0 reduces 16 -> DSMEM slots
// of all 8 peers; one barrier.cluster; every warp reduces 8 slots ->
// next centroid in registers. Skipped groups keep cached meta => output
// bit-identical to brute force.

#define NB       8
#define NPTS     131072
#define NSAMP    1024
#define CSIZE    8
#define TPB      512
#define PPB      (NPTS / CSIZE)      // 16384 points per CTA
#define NWARPS   (TPB / 32)          // 16
#define NCELLS   32768               // 32^3 Morton cells
#define GRPSZ    64
#define NGRP_C   256                 // groups per CTA
#define GPW      (NGRP_C / NWARPS)   // 16 groups per warp

static __device__ float4   g_reorder[NB][NPTS];    // 16 MB scratch (L2-resident)
static __device__ unsigned g_hist[NB][NCELLS];     // re-zeroed every launch

struct __align__(16) Red { unsigned v, i; float x, y, z; unsigned pad[3]; };  // 32B

struct Smem {
    float    mind[NGRP_C * GRPSZ];   // 64 KB per-point mindist
    float4   gsph[NGRP_C];           // center.xyz, inflated radius
    Red      meta[NGRP_C];           // cached {maxdist, argidx, coords}
    Red      warpred[NWARPS];
    Red      slots[2][CSIZE];
    unsigned scanp[TPB];
};

// ---------- asm helpers ----------
__device__ __forceinline__ unsigned ctarank() {
    unsigned r; asm("mov.u32 %0, %%cluster_ctarank;" : "=r"(r)); return r;
}
__device__ __forceinline__ unsigned cvta_s(const void* p) {
    unsigned r;
    asm("{ .reg .u64 t; cvta.to.shared.u64 t, %1; cvt.u32.u64 %0, t; }"
        : "=r"(r) : "l"(p));
    return r;
}
__device__ __forceinline__ unsigned mapa_s(unsigned laddr, unsigned rank) {
    unsigned r;
    asm("mapa.shared::cluster.u32 %0, %1, %2;" : "=r"(r) : "r"(laddr), "r"(rank));
    return r;
}
__device__ __forceinline__ void st_cluster_v4(unsigned raddr, unsigned a, unsigned b,
                                              unsigned c, unsigned d) {
    asm volatile("st.shared::cluster.v4.b32 [%0], {%1,%2,%3,%4};"
                 :: "r"(raddr), "r"(a), "r"(b), "r"(c), "r"(d) : "memory");
}
__device__ __forceinline__ void st_cluster_u32(unsigned raddr, unsigned v) {
    asm volatile("st.shared::cluster.u32 [%0], %1;" :: "r"(raddr), "r"(v) : "memory");
}
__device__ __forceinline__ void cluster_bar() {
    asm volatile("barrier.cluster.arrive.aligned;" ::: "memory");
    asm volatile("barrier.cluster.wait.aligned;"   ::: "memory");
}
__device__ __forceinline__ unsigned p1b2(unsigned x) {
    x &= 0x3ffu;
    x = (x | (x << 16)) & 0x030000FFu;
    x = (x | (x << 8))  & 0x0300F00Fu;
    x = (x | (x << 4))  & 0x030C30C3u;
    x = (x | (x << 2))  & 0x09249249u;
    return x;
}
__device__ __forceinline__ unsigned cell_of(float x, float y, float z) {
    int cx = (int)((x + 5.0f) * 3.2f); cx = cx < 0 ? 0 : (cx > 31 ? 31 : cx);
    int cy = (int)((y + 5.0f) * 3.2f); cy = cy < 0 ? 0 : (cy > 31 ? 31 : cy);
    int cz = (int)((z + 5.0f) * 3.2f); cz = cz < 0 ? 0 : (cz > 31 ? 31 : cz);
    return p1b2((unsigned)cx) | (p1b2((unsigned)cy) << 1) | (p1b2((unsigned)cz) << 2);
}

__global__ void __launch_bounds__(TPB, 1)
fps_kernel(const float* __restrict__ xyz, float* __restrict__ out) {
    extern __shared__ __align__(16) unsigned char smem_raw[];
    Smem* s = reinterpret_cast<Smem*>(smem_raw);

    const int      tid  = threadIdx.x;
    const unsigned lane = tid & 31;
    const unsigned warp = (unsigned)tid >> 5;
    const unsigned rank = ctarank();
    const int      batch = blockIdx.x / CSIZE;

    const float* __restrict__ base = xyz + (size_t)batch * NPTS * 3;
    unsigned* __restrict__ hb = g_hist[batch];
    float4*   __restrict__ rb = g_reorder[batch];

    // ================= one-time spatial binning (as R9, verified) ==========
    for (int i = (int)rank * (NCELLS / CSIZE) + tid;
         i < (int)(rank + 1) * (NCELLS / CSIZE); i += TPB)
        hb[i] = 0u;
    cluster_bar();

    for (int ii = tid; ii < PPB; ii += TPB) {
        unsigned gi = rank * PPB + (unsigned)ii;
        const float* p = base + (size_t)gi * 3;
        float x = __ldg(p), y = __ldg(p + 1), z = __ldg(p + 2);
        atomicAdd(&hb[cell_of(x, y, z)], 1u);
    }
    cluster_bar();

    if (rank == 0) {
        const int per = NCELLS / TPB;        // 64
        unsigned ssum = 0;
        for (int j = 0; j < per; ++j) ssum += hb[tid * per + j];
        s->scanp[tid] = ssum;
        __syncthreads();
        if (tid == 0) {
            unsigned run = 0;
            for (int i = 0; i < TPB; ++i) { unsigned v = s->scanp[i]; s->scanp[i] = run; run += v; }
        }
        __syncthreads();
        unsigned run = s->scanp[tid];
        for (int j = 0; j < per; ++j) {
            unsigned v = hb[tid * per + j];
            hb[tid * per + j] = run;
            run += v;
        }
    }
    cluster_bar();

    for (int ii = tid; ii < PPB; ii += TPB) {
        unsigned gi = rank * PPB + (unsigned)ii;
        const float* p = base + (size_t)gi * 3;
        float x = __ldg(p), y = __ldg(p + 1), z = __ldg(p + 2);
        unsigned slot = atomicAdd(&hb[cell_of(x, y, z)], 1u);
        rb[slot] = make_float4(x, y, z, __uint_as_float(gi));
    }
    cluster_bar();

    // build per-group bounding spheres + init mindist/meta
    for (int i = tid; i < NGRP_C * GRPSZ; i += TPB)
        s->mind[i] = __int_as_float(0x7f800000);
    for (int kk = 0; kk < GPW; ++kk) {
        int k = (int)warp * GPW + kk;
        const float4* rp = rb + ((unsigned)k * CSIZE + rank) * GRPSZ;
        float4 p0 = __ldg(rp + 2 * lane);
        float4 p1 = __ldg(rp + 2 * lane + 1);
        float sx = p0.x + p1.x, sy = p0.y + p1.y, sz = p0.z + p1.z;
#pragma unroll
        for (int off = 16; off > 0; off >>= 1) {
            sx += __shfl_xor_sync(0xffffffffu, sx, off);
            sy += __shfl_xor_sync(0xffffffffu, sy, off);
            sz += __shfl_xor_sync(0xffffffffu, sz, off);
        }
        float gx = sx * (1.0f / GRPSZ), gy = sy * (1.0f / GRPSZ), gz = sz * (1.0f / GRPSZ);
        float dx0 = p0.x - gx, dy0 = p0.y - gy, dz0 = p0.z - gz;
        float dx1 = p1.x - gx, dy1 = p1.y - gy, dz1 = p1.z - gz;
        float d2 = fmaxf(dx0 * dx0 + dy0 * dy0 + dz0 * dz0,
                         dx1 * dx1 + dy1 * dy1 + dz1 * dz1);
        unsigned md = __reduce_max_sync(0xffffffffu, __float_as_uint(d2));
        if (lane == 0) {
            float rad = sqrtf(__uint_as_float(md)) * 1.001f + 1e-6f;
            s->gsph[k] = make_float4(gx, gy, gz, rad);
            s->meta[k].v = 0x7f800000u;   // +inf: never skipped in step 1
            s->meta[k].i = 0u;
        }
    }

    unsigned rs0 = 0, rs1 = 0;
    if (warp == 0 && lane < CSIZE) {
        rs0 = mapa_s(cvta_s(&s->slots[0][rank]), lane);
        rs1 = mapa_s(cvta_s(&s->slots[1][rank]), lane);
    }

    float cx = __ldg(base + 0);
    float cy = __ldg(base + 1);
    float cz = __ldg(base + 2);
    if (rank == 0 && tid == 0) {
        float* o = out + (size_t)batch * NSAMP * 3;
        o[0] = cx; o[1] = cy; o[2] = cz;
    }
    __syncthreads();
    cluster_bar();   // spheres/mindist ready everywhere before step 1

    // ================= steady-state FPS loop =================
    for (int t = 1; t < NSAMP; ++t) {
        // ---- check: lane j tests group j*16+warp (no atomics, no queue) ----
        bool act = false;
        if (lane < GPW) {
            int k = (int)lane * NWARPS + (int)warp;
            float4 gs = s->gsph[k];
            float gmax = __uint_as_float(s->meta[k].v);
            float dx = gs.x - cx, dy = gs.y - cy, dz = gs.z - cz;
            float dc2 = dx * dx + dy * dy + dz * dz;
            float tt = sqrtf(dc2) - gs.w;
            act = !((tt > 0.0f) && (0.998f * tt * tt > gmax));
        }
        unsigned mask = __ballot_sync(0xffffffffu, act);

        // ---- work loop with 1-group prefetch pipeline ----
        int kcur = -1; float4 a0, a1;
        if (mask) {
            int j = __ffs(mask) - 1; mask &= mask - 1u;
            kcur = j * NWARPS + (int)warp;
            const float4* rp = rb + ((unsigned)kcur * CSIZE + rank) * GRPSZ;
            a0 = __ldg(rp + 2 * lane);
            a1 = __ldg(rp + 2 * lane + 1);
        }
        while (kcur >= 0) {
            int knext = -1; float4 n0, n1;
            if (mask) {
                int j = __ffs(mask) - 1; mask &= mask - 1u;
                knext = j * NWARPS + (int)warp;
                const float4* rp = rb + ((unsigned)knext * CSIZE + rank) * GRPSZ;
                n0 = __ldg(rp + 2 * lane);
                n1 = __ldg(rp + 2 * lane + 1);
            }
            // process kcur
            float2* mp = reinterpret_cast<float2*>(&s->mind[kcur * GRPSZ + 2 * lane]);
            float2 mo = *mp;
            float dx = a0.x - cx, dy = a0.y - cy, dz = a0.z - cz;
            float d0 = dx * dx; d0 = fmaf(dy, dy, d0); d0 = fmaf(dz, dz, d0);
            dx = a1.x - cx; dy = a1.y - cy; dz = a1.z - cz;
            float d1 = dx * dx; d1 = fmaf(dy, dy, d1); d1 = fmaf(dz, dz, d1);
            float mm0 = fminf(mo.x, d0);
            float mm1 = fminf(mo.y, d1);
            *mp = make_float2(mm0, mm1);

            unsigned i0 = __float_as_uint(a0.w), i1 = __float_as_uint(a1.w);
            float bv = fmaxf(mm0, mm1);
            bool t0 = (mm0 == bv), t1 = (mm1 == bv);
            unsigned bi = t0 ? (t1 ? min(i0, i1) : i0) : i1;
            bool pick0 = t0 && (!t1 || i0 < i1);
            float bx = pick0 ? a0.x : a1.x;
            float by = pick0 ? a0.y : a1.y;
            float bz = pick0 ? a0.z : a1.z;

            unsigned vb = __float_as_uint(bv);
            unsigned wv = __reduce_max_sync(0xffffffffu, vb);
            unsigned cd = (vb == wv) ? bi : 0xffffffffu;
            unsigned wi = __reduce_min_sync(0xffffffffu, cd);
            if (vb == wv && bi == wi) {                    // unique (indices unique)
                *reinterpret_cast<uint4*>(&s->meta[kcur]) =
                    make_uint4(wv, wi, __float_as_uint(bx), __float_as_uint(by));
                s->meta[kcur].z = bz;
            }
            kcur = knext; a0 = n0; a1 = n1;
        }

        // ---- warp reduces its own 16 metas -> warpred[warp] ----
        {
            unsigned v = 0, i = 0xffffffffu, xw = 0, yw = 0, zw = 0;
            if (lane < GPW) {
                int k = (int)lane * NWARPS + (int)warp;
                uint4 w4 = *reinterpret_cast<const uint4*>(&s->meta[k]);
                v = w4.x; i = w4.y; xw = w4.z; yw = w4.w;
                zw = __float_as_uint(s->meta[k].z);
            }
            unsigned bv = __reduce_max_sync(0xffffffffu, v);
            unsigned bc = (v == bv) ? i : 0xffffffffu;
            unsigned bi = __reduce_min_sync(0xffffffffu, bc);
            unsigned msk = __ballot_sync(0xffffffffu, bc == bi);
            int L = __ffs(msk) - 1;
            if ((int)lane == L) {
                *reinterpret_cast<uint4*>(&s->warpred[warp]) =
                    make_uint4(bv, bi, xw, yw);
                s->warpred[warp].z = __uint_as_float(zw);
            }
        }
        __syncthreads();

        const int par = t & 1;

        // ---- warp0: reduce 16 warp partials, push to all 8 peers ----
        if (warp == 0) {
            unsigned v = 0, i = 0xffffffffu, xw = 0, yw = 0, zw = 0;
            if (lane < NWARPS) {
                uint4 w4 = *reinterpret_cast<const uint4*>(&s->warpred[lane]);
                v = w4.x; i = w4.y; xw = w4.z; yw = w4.w;
                zw = __float_as_uint(s->warpred[lane].z);
            }
            unsigned bv = __reduce_max_sync(0xffffffffu, v);
            unsigned bc = (v == bv) ? i : 0xffffffffu;
            unsigned bi = __reduce_min_sync(0xffffffffu, bc);
            unsigned msk = __ballot_sync(0xffffffffu, bc == bi);
            int L = __ffs(msk) - 1;
            xw = __shfl_sync(0xffffffffu, xw, L);
            yw = __shfl_sync(0xffffffffu, yw, L);
            zw = __shfl_sync(0xffffffffu, zw, L);
            if (lane < CSIZE) {
                unsigned ra = par ? rs1 : rs0;
                st_cluster_v4(ra, bv, bi, xw, yw);
                st_cluster_u32(ra + 16, zw);
            }
        }

        cluster_bar();   // one cluster barrier per step

        // ---- EVERY warp reduces the 8 slots -> next centroid in registers ----
        {
            unsigned v = 0, i = 0xffffffffu, xw = 0, yw = 0, zw = 0;
            if (lane < CSIZE) {
                uint4 w4 = *reinterpret_cast<const uint4*>(&s->slots[par][lane]);
                v = w4.x; i = w4.y; xw = w4.z; yw = w4.w;
                zw = __float_as_uint(s->slots[par][lane].z);
            }
            unsigned cv = __reduce_max_sync(0xffffffffu, v);
            unsigned cc = (v == cv) ? i : 0xffffffffu;
            unsigned ci = __reduce_min_sync(0xffffffffu, cc);
            unsigned msk = __ballot_sync(0xffffffffu, cc == ci);
            int W = __ffs(msk) - 1;
            cx = __uint_as_float(__shfl_sync(0xffffffffu, xw, W));
            cy = __uint_as_float(__shfl_sync(0xffffffffu, yw, W));
            cz = __uint_as_float(__shfl_sync(0xffffffffu, zw, W));
            if (rank == 0 && tid == 0) {
                float* o = out + ((size_t)batch * NSAMP + (size_t)t) * 3;
                o[0] = cx; o[1] = cy; o[2] = cz;
            }
        }
        // hazards: meta/mind are owner-warp-private; warpred[w] is written by
        // warp w and read by warp0 between the __syncthreads and warp0's
        // cluster-bar arrive (no warp can pass the cluster bar before warp0
        // arrives); slots are parity double-buffered across cluster barriers.
    }

    cluster_bar();  // keep CTAs alive until all DSMEM traffic has landed
}

extern "C" void kernel_launch(void* const* d_in, const int* in_sizes, int n_in,
                              void* d_out, int out_size) {
    (void)in_sizes; (void)n_in; (void)out_size;
    const float* xyz = (const float*)d_in[0];
    float* out = (float*)d_out;

    cudaFuncSetAttribute(fps_kernel,
                         cudaFuncAttributeMaxDynamicSharedMemorySize,
                         (int)sizeof(Smem));

    cudaLaunchConfig_t cfg = {};
    cfg.gridDim  = dim3(NB * CSIZE, 1, 1);   // 64 CTAs
    cfg.blockDim = dim3(TPB, 1, 1);
    cfg.dynamicSmemBytes = sizeof(Smem);
    cfg.stream = 0;

    cudaLaunchAttribute attr[1];
    attr[0].id = cudaLaunchAttributeClusterDimension;
    attr[0].val.clusterDim.x = CSIZE;
    attr[0].val.clusterDim.y = 1;
    attr[0].val.clusterDim.z = 1;
    cfg.attrs = attr;
    cfg.numAttrs = 1;

    cudaLaunchKernelEx(&cfg, fps_kernel, xyz, out);
}

// round 11
// speedup vs baseline: 1.1773x; 1.1773x over previous
#include <cuda_runtime.h>
#include <cstdint>
#include <cstddef>

// FPS with EXACT spatial pruning + balanced bitmap work distribution.
// B=8, N=131072, NPOINT=1024. 8 clusters x 8 CTAs x 512 threads.
// One-time Morton(32^3) counting sort -> g_reorder (xyz + orig idx).
// 256 groups/CTA of 64 pts. Per step:
//   check: threads 0..255 test the exact skip bound -> 256-bit bitmap (ballot)
//   work:  warp w processes active ranks w, w+16, ... (popc+__fns enumeration,
//          2-deep L2 prefetch pipeline) -> update SMEM mindist, REDUX -> meta
//   reduce: each warp REDUXes 16 metas -> warpred; warp0 reduces 16 ->
//          DSMEM slots of all 8 peers; one barrier.cluster; every warp
//          reduces 8 slots -> next centroid in registers.
// Skipped groups keep cached meta => output bit-identical to brute force.

#define NB       8
#define NPTS     131072
#define NSAMP    1024
#define CSIZE    8
#define TPB      512
#define PPB      (NPTS / CSIZE)      // 16384 points per CTA
#define NWARPS   (TPB / 32)          // 16
#define NCELLS   32768               // 32^3 Morton cells
#define GRPSZ    64
#define NGRP_C   256                 // groups per CTA
#define GPW      (NGRP_C / NWARPS)   // 16 (meta-reduce mapping)
#define NBMW     (NGRP_C / 32)       // 8 bitmap words

static __device__ float4   g_reorder[NB][NPTS];    // 16 MB scratch (L2-resident)
static __device__ unsigned g_hist[NB][NCELLS];     // re-zeroed every launch

struct __align__(16) Red { unsigned v, i; float x, y, z; unsigned pad[3]; };  // 32B

struct Smem {
    float    mind[NGRP_C * GRPSZ];   // 64 KB per-point mindist
    float4   gsph[NGRP_C];           // center.xyz, inflated radius
    Red      meta[NGRP_C];           // cached {maxdist, argidx, coords}
    Red      warpred[NWARPS];
    Red      slots[2][CSIZE];
    unsigned bitmap[NBMW];
    unsigned scanp[TPB];
};

// ---------- asm helpers ----------
__device__ __forceinline__ unsigned ctarank() {
    unsigned r; asm("mov.u32 %0, %%cluster_ctarank;" : "=r"(r)); return r;
}
__device__ __forceinline__ unsigned cvta_s(const void* p) {
    unsigned r;
    asm("{ .reg .u64 t; cvta.to.shared.u64 t, %1; cvt.u32.u64 %0, t; }"
        : "=r"(r) : "l"(p));
    return r;
}
__device__ __forceinline__ unsigned mapa_s(unsigned laddr, unsigned rank) {
    unsigned r;
    asm("mapa.shared::cluster.u32 %0, %1, %2;" : "=r"(r) : "r"(laddr), "r"(rank));
    return r;
}
__device__ __forceinline__ void st_cluster_v4(unsigned raddr, unsigned a, unsigned b,
                                              unsigned c, unsigned d) {
    asm volatile("st.shared::cluster.v4.b32 [%0], {%1,%2,%3,%4};"
                 :: "r"(raddr), "r"(a), "r"(b), "r"(c), "r"(d) : "memory");
}
__device__ __forceinline__ void st_cluster_u32(unsigned raddr, unsigned v) {
    asm volatile("st.shared::cluster.u32 [%0], %1;" :: "r"(raddr), "r"(v) : "memory");
}
__device__ __forceinline__ void cluster_bar() {
    asm volatile("barrier.cluster.arrive.aligned;" ::: "memory");
    asm volatile("barrier.cluster.wait.aligned;"   ::: "memory");
}
__device__ __forceinline__ unsigned p1b2(unsigned x) {
    x &= 0x3ffu;
    x = (x | (x << 16)) & 0x030000FFu;
    x = (x | (x << 8))  & 0x0300F00Fu;
    x = (x | (x << 4))  & 0x030C30C3u;
    x = (x | (x << 2))  & 0x09249249u;
    return x;
}
__device__ __forceinline__ unsigned cell_of(float x, float y, float z) {
    int cx = (int)((x + 5.0f) * 3.2f); cx = cx < 0 ? 0 : (cx > 31 ? 31 : cx);
    int cy = (int)((y + 5.0f) * 3.2f); cy = cy < 0 ? 0 : (cy > 31 ? 31 : cy);
    int cz = (int)((z + 5.0f) * 3.2f); cz = cz < 0 ? 0 : (cz > 31 ? 31 : cz);
    return p1b2((unsigned)cx) | (p1b2((unsigned)cy) << 1) | (p1b2((unsigned)cz) << 2);
}
// r-th (0-based) set bit over the 8-word bitmap; caller guarantees r < total
__device__ __forceinline__ int kth_set_bit(const unsigned* bm, int r) {
#pragma unroll
    for (int w = 0; w < NBMW; ++w) {
        int c = __popc(bm[w]);
        if (r < c) return w * 32 + (int)__fns(bm[w], 0, r + 1);
        r -= c;
    }
    return -1;
}

__global__ void __launch_bounds__(TPB, 1)
fps_kernel(const float* __restrict__ xyz, float* __restrict__ out) {
    extern __shared__ __align__(16) unsigned char smem_raw[];
    Smem* s = reinterpret_cast<Smem*>(smem_raw);

    const int      tid  = threadIdx.x;
    const unsigned lane = tid & 31;
    const unsigned warp = (unsigned)tid >> 5;
    const unsigned rank = ctarank();
    const int      batch = blockIdx.x / CSIZE;

    const float* __restrict__ base = xyz + (size_t)batch * NPTS * 3;
    unsigned* __restrict__ hb = g_hist[batch];
    float4*   __restrict__ rb = g_reorder[batch];

    // ================= one-time spatial binning (R9/R10, verified) =========
    for (int i = (int)rank * (NCELLS / CSIZE) + tid;
         i < (int)(rank + 1) * (NCELLS / CSIZE); i += TPB)
        hb[i] = 0u;
    cluster_bar();

    for (int ii = tid; ii < PPB; ii += TPB) {
        unsigned gi = rank * PPB + (unsigned)ii;
        const float* p = base + (size_t)gi * 3;
        float x = __ldg(p), y = __ldg(p + 1), z = __ldg(p + 2);
        atomicAdd(&hb[cell_of(x, y, z)], 1u);
    }
    cluster_bar();

    if (rank == 0) {
        const int per = NCELLS / TPB;        // 64
        unsigned ssum = 0;
        for (int j = 0; j < per; ++j) ssum += hb[tid * per + j];
        s->scanp[tid] = ssum;
        __syncthreads();
        if (tid == 0) {
            unsigned run = 0;
            for (int i = 0; i < TPB; ++i) { unsigned v = s->scanp[i]; s->scanp[i] = run; run += v; }
        }
        __syncthreads();
        unsigned run = s->scanp[tid];
        for (int j = 0; j < per; ++j) {
            unsigned v = hb[tid * per + j];
            hb[tid * per + j] = run;
            run += v;
        }
    }
    cluster_bar();

    for (int ii = tid; ii < PPB; ii += TPB) {
        unsigned gi = rank * PPB + (unsigned)ii;
        const float* p = base + (size_t)gi * 3;
        float x = __ldg(p), y = __ldg(p + 1), z = __ldg(p + 2);
        unsigned slot = atomicAdd(&hb[cell_of(x, y, z)], 1u);
        rb[slot] = make_float4(x, y, z, __uint_as_float(gi));
    }
    cluster_bar();

    // per-group bounding spheres + init mindist/meta
    for (int i = tid; i < NGRP_C * GRPSZ; i += TPB)
        s->mind[i] = __int_as_float(0x7f800000);
    for (int kk = 0; kk < GPW; ++kk) {
        int k = (int)warp * GPW + kk;
        const float4* rp = rb + ((unsigned)k * CSIZE + rank) * GRPSZ;
        float4 p0 = __ldg(rp + 2 * lane);
        float4 p1 = __ldg(rp + 2 * lane + 1);
        float sx = p0.x + p1.x, sy = p0.y + p1.y, sz = p0.z + p1.z;
#pragma unroll
        for (int off = 16; off > 0; off >>= 1) {
            sx += __shfl_xor_sync(0xffffffffu, sx, off);
            sy += __shfl_xor_sync(0xffffffffu, sy, off);
            sz += __shfl_xor_sync(0xffffffffu, sz, off);
        }
        float gx = sx * (1.0f / GRPSZ), gy = sy * (1.0f / GRPSZ), gz = sz * (1.0f / GRPSZ);
        float dx0 = p0.x - gx, dy0 = p0.y - gy, dz0 = p0.z - gz;
        float dx1 = p1.x - gx, dy1 = p1.y - gy, dz1 = p1.z - gz;
        float d2 = fmaxf(dx0 * dx0 + dy0 * dy0 + dz0 * dz0,
                         dx1 * dx1 + dy1 * dy1 + dz1 * dz1);
        unsigned md = __reduce_max_sync(0xffffffffu, __float_as_uint(d2));
        if (lane == 0) {
            float rad = sqrtf(__uint_as_float(md)) * 1.001f + 1e-6f;
            s->gsph[k] = make_float4(gx, gy, gz, rad);
            s->meta[k].v = 0x7f800000u;   // +inf: never skipped in step 1
            s->meta[k].i = 0u;
        }
    }

    unsigned rs0 = 0, rs1 = 0;
    if (warp == 0 && lane < CSIZE) {
        rs0 = mapa_s(cvta_s(&s->slots[0][rank]), lane);
        rs1 = mapa_s(cvta_s(&s->slots[1][rank]), lane);
    }

    float cx = __ldg(base + 0);
    float cy = __ldg(base + 1);
    float cz = __ldg(base + 2);
    if (rank == 0 && tid == 0) {
        float* o = out + (size_t)batch * NSAMP * 3;
        o[0] = cx; o[1] = cy; o[2] = cz;
    }
    __syncthreads();
    cluster_bar();   // spheres/mindist ready everywhere before step 1

    // ================= steady-state FPS loop =================
    for (int t = 1; t < NSAMP; ++t) {
        // ---- check: warps 0..7 test groups warp*32+lane -> bitmap ----
        if (warp < NBMW) {
            int k = (int)warp * 32 + (int)lane;
            float4 gs = s->gsph[k];
            float gmax = __uint_as_float(s->meta[k].v);
            float dx = gs.x - cx, dy = gs.y - cy, dz = gs.z - cz;
            float dc2 = dx * dx + dy * dy + dz * dz;
            float tt = sqrtf(dc2) - gs.w;
            bool act = !((tt > 0.0f) && (0.998f * tt * tt > gmax));
            unsigned bal = __ballot_sync(0xffffffffu, act);
            if (lane == 0) s->bitmap[warp] = bal;
        }
        __syncthreads();

        // ---- every warp reads the bitmap, takes active ranks w, w+16, ... --
        unsigned bm[NBMW];
        int na = 0;
#pragma unroll
        for (int w = 0; w < NBMW; ++w) { bm[w] = s->bitmap[w]; na += __popc(bm[w]); }

        int r = (int)warp;
        int kcur = -1; float4 a0 = {}, a1 = {};
        if (r < na) {
            kcur = kth_set_bit(bm, r); r += NWARPS;
            const float4* rp = rb + ((unsigned)kcur * CSIZE + rank) * GRPSZ;
            a0 = __ldg(rp + 2 * lane);
            a1 = __ldg(rp + 2 * lane + 1);
        }
        while (kcur >= 0) {
            int knext = -1; float4 n0 = {}, n1 = {};
            if (r < na) {
                knext = kth_set_bit(bm, r); r += NWARPS;
                const float4* rp = rb + ((unsigned)knext * CSIZE + rank) * GRPSZ;
                n0 = __ldg(rp + 2 * lane);
                n1 = __ldg(rp + 2 * lane + 1);
            }
            // process kcur
            float2* mp = reinterpret_cast<float2*>(&s->mind[kcur * GRPSZ + 2 * lane]);
            float2 mo = *mp;
            float dx = a0.x - cx, dy = a0.y - cy, dz = a0.z - cz;
            float d0 = dx * dx; d0 = fmaf(dy, dy, d0); d0 = fmaf(dz, dz, d0);
            dx = a1.x - cx; dy = a1.y - cy; dz = a1.z - cz;
            float d1 = dx * dx; d1 = fmaf(dy, dy, d1); d1 = fmaf(dz, dz, d1);
            float mm0 = fminf(mo.x, d0);
            float mm1 = fminf(mo.y, d1);
            *mp = make_float2(mm0, mm1);

            unsigned i0 = __float_as_uint(a0.w), i1 = __float_as_uint(a1.w);
            float bv = fmaxf(mm0, mm1);
            bool t0 = (mm0 == bv), t1 = (mm1 == bv);
            unsigned bi = t0 ? (t1 ? min(i0, i1) : i0) : i1;
            bool pick0 = t0 && (!t1 || i0 < i1);
            float bx = pick0 ? a0.x : a1.x;
            float by = pick0 ? a0.y : a1.y;
            float bz = pick0 ? a0.z : a1.z;

            unsigned vb = __float_as_uint(bv);
            unsigned wv = __reduce_max_sync(0xffffffffu, vb);
            unsigned cd = (vb == wv) ? bi : 0xffffffffu;
            unsigned wi = __reduce_min_sync(0xffffffffu, cd);
            if (vb == wv && bi == wi) {                    // unique (indices unique)
                *reinterpret_cast<uint4*>(&s->meta[kcur]) =
                    make_uint4(wv, wi, __float_as_uint(bx), __float_as_uint(by));
                s->meta[kcur].z = bz;
            }
            kcur = knext; a0 = n0; a1 = n1;
        }
        __syncthreads();   // metas cross-warp-written: fence before meta reduce

        // ---- warp reduces 16 metas (static mapping) -> warpred[warp] ----
        {
            unsigned v = 0, i = 0xffffffffu, xw = 0, yw = 0, zw = 0;
            if (lane < GPW) {
                int k = (int)lane * NWARPS + (int)warp;
                uint4 w4 = *reinterpret_cast<const uint4*>(&s->meta[k]);
                v = w4.x; i = w4.y; xw = w4.z; yw = w4.w;
                zw = __float_as_uint(s->meta[k].z);
            }
            unsigned bv = __reduce_max_sync(0xffffffffu, v);
            unsigned bc = (v == bv) ? i : 0xffffffffu;
            unsigned bi = __reduce_min_sync(0xffffffffu, bc);
            unsigned msk = __ballot_sync(0xffffffffu, bc == bi);
            int L = __ffs(msk) - 1;
            if ((int)lane == L) {
                *reinterpret_cast<uint4*>(&s->warpred[warp]) =
                    make_uint4(bv, bi, xw, yw);
                s->warpred[warp].z = __uint_as_float(zw);
            }
        }
        __syncthreads();

        const int par = t & 1;

        // ---- warp0: reduce 16 warp partials, push to all 8 peers ----
        if (warp == 0) {
            unsigned v = 0, i = 0xffffffffu, xw = 0, yw = 0, zw = 0;
            if (lane < NWARPS) {
                uint4 w4 = *reinterpret_cast<const uint4*>(&s->warpred[lane]);
                v = w4.x; i = w4.y; xw = w4.z; yw = w4.w;
                zw = __float_as_uint(s->warpred[lane].z);
            }
            unsigned bv = __reduce_max_sync(0xffffffffu, v);
            unsigned bc = (v == bv) ? i : 0xffffffffu;
            unsigned bi = __reduce_min_sync(0xffffffffu, bc);
            unsigned msk = __ballot_sync(0xffffffffu, bc == bi);
            int L = __ffs(msk) - 1;
            xw = __shfl_sync(0xffffffffu, xw, L);
            yw = __shfl_sync(0xffffffffu, yw, L);
            zw = __shfl_sync(0xffffffffu, zw, L);
            if (lane < CSIZE) {
                unsigned ra = par ? rs1 : rs0;
                st_cluster_v4(ra, bv, bi, xw, yw);
                st_cluster_u32(ra + 16, zw);
            }
        }

        cluster_bar();   // one cluster barrier per step

        // ---- EVERY warp reduces the 8 slots -> next centroid in registers ----
        {
            unsigned v = 0, i = 0xffffffffu, xw = 0, yw = 0, zw = 0;
            if (lane < CSIZE) {
                uint4 w4 = *reinterpret_cast<const uint4*>(&s->slots[par][lane]);
                v = w4.x; i = w4.y; xw = w4.z; yw = w4.w;
                zw = __float_as_uint(s->slots[par][lane].z);
            }
            unsigned cv = __reduce_max_sync(0xffffffffu, v);
            unsigned cc = (v == cv) ? i : 0xffffffffu;
            unsigned ci = __reduce_min_sync(0xffffffffu, cc);
            unsigned msk = __ballot_sync(0xffffffffu, cc == ci);
            int W = __ffs(msk) - 1;
            cx = __uint_as_float(__shfl_sync(0xffffffffu, xw, W));
            cy = __uint_as_float(__shfl_sync(0xffffffffu, yw, W));
            cz = __uint_as_float(__shfl_sync(0xffffffffu, zw, W));
            if (rank == 0 && tid == 0) {
                float* o = out + ((size_t)batch * NSAMP + (size_t)t) * 3;
                o[0] = cx; o[1] = cy; o[2] = cz;
            }
        }
        // hazards: bitmap written by warps 0..7, read after __syncthreads;
        // meta written in work loop, read after __syncthreads; warpred[w]
        // written by warp w, read by warp0 after __syncthreads; slots parity
        // double-buffered across the cluster barrier (proven in R3..R10).
    }

    cluster_bar();  // keep CTAs alive until all DSMEM traffic has landed
}

extern "C" void kernel_launch(void* const* d_in, const int* in_sizes, int n_in,
                              void* d_out, int out_size) {
    (void)in_sizes; (void)n_in; (void)out_size;
    const float* xyz = (const float*)d_in[0];
    float* out = (float*)d_out;

    cudaFuncSetAttribute(fps_kernel,
                         cudaFuncAttributeMaxDynamicSharedMemorySize,
                         (int)sizeof(Smem));

    cudaLaunchConfig_t cfg = {};
    cfg.gridDim  = dim3(NB * CSIZE, 1, 1);   // 64 CTAs
    cfg.blockDim = dim3(TPB, 1, 1);
    cfg.dynamicSmemBytes = sizeof(Smem);
    cfg.stream = 0;

    cudaLaunchAttribute attr[1];
    attr[0].id = cudaLaunchAttributeClusterDimension;
    attr[0].val.clusterDim.x = CSIZE;
    attr[0].val.clusterDim.y = 1;
    attr[0].val.clusterDim.z = 1;
    cfg.attrs = attr;
    cfg.numAttrs = 1;

    cudaLaunchKernelEx(&cfg, fps_kernel, xyz, out);
}